// round 14
// baseline (speedup 1.0000x reference)
#include <cuda_runtime.h>
#include <cuda_bf16.h>
#include <cuda_fp16.h>
#include <math.h>

#define NNODES 100000
#define FIN    512
#define HID    256
#define NC     40
#define KSTEPS 10
#define EMAX   3200000
#define ALPHA  0.1f

// ---------------- device scratch (no allocations allowed) ----------------
__device__ __half g_hid16[NNODES * HID];   // 51 MB (fp16 hid)
__device__ __half g_h16 [NNODES * NC];     // 8 MB (fp16 h: gather + inject)
__device__ __half g_z16A[NNODES * NC];     // 8 MB ping
__device__ __half g_z16B[NNODES * NC];     // 8 MB pong
__device__ float g_dinv[NNODES];
__device__ int   g_deg [NNODES];
__device__ int   g_rowptr[NNODES + 1];
__device__ int   g_fill[NNODES];
__device__ int2  g_edge[EMAX];             // (col, ew bits) packed

// fp16 W (transposed) for tensor-core gemm1 (x is fp16-converted in-kernel)
__device__ __half g_wT[HID * FIN];         // [n][k], 0.26 MB

// ---------------- graph preprocessing ----------------
__global__ void zero_deg_kernel() {
    int i = blockIdx.x * blockDim.x + threadIdx.x;
    if (i < NNODES) g_deg[i] = 0;
}

__global__ void count_deg_kernel(const int* __restrict__ ei, int E) {
    int e = blockIdx.x * blockDim.x + threadIdx.x;
    if (e < E) atomicAdd(&g_deg[ei[e]], 1);
}

__global__ void scan_kernel(int E) {
    const int T = 1024;
    const int CH = (NNODES + T - 1) / T;
    int t = threadIdx.x;
    int beg = t * CH;
    int end = beg + CH; if (end > NNODES) end = NNODES;
    if (beg > NNODES) beg = NNODES;

    int sum = 0;
    for (int i = beg; i < end; i++) sum += g_deg[i];

    __shared__ int sh[1024];
    sh[t] = sum;
    __syncthreads();
    for (int off = 1; off < T; off <<= 1) {
        int v = (t >= off) ? sh[t - off] : 0;
        __syncthreads();
        sh[t] += v;
        __syncthreads();
    }
    int offset = sh[t] - sum;

    int running = offset;
    for (int i = beg; i < end; i++) {
        g_rowptr[i] = running;
        g_fill[i]   = running;
        g_dinv[i]   = rsqrtf((float)(g_deg[i] + 1));   // +1 self-loop
        running += g_deg[i];
    }
    if (t == T - 1) g_rowptr[NNODES] = sh[T - 1];
}

__global__ void scatter_kernel(const int* __restrict__ ei, int E) {
    int e = blockIdx.x * blockDim.x + threadIdx.x;
    if (e >= E) return;
    int r = ei[e];          // destination
    int c = ei[E + e];      // source
    int pos = atomicAdd(&g_fill[r], 1);
    g_edge[pos] = make_int2(c, __float_as_int(g_dinv[r] * g_dinv[c]));
}

// ---------------- W fp16 conversion (tiny: 0.26 MB) ----------------
__global__ void convert_w_kernel(const float* __restrict__ W1) {
    int i = blockIdx.x * blockDim.x + threadIdx.x;     // over FIN*HID
    if (i >= FIN * HID) return;
    int k = i / HID, n = i - k * HID;
    g_wT[n * FIN + k] = __float2half_rn(W1[i]);
}

// ---------------- helpers for mma path ----------------
__device__ __forceinline__ unsigned smem_u32(const void* p) {
    return (unsigned)__cvta_generic_to_shared(p);
}
__device__ __forceinline__ void cpasync16(unsigned saddr, const void* gaddr) {
    asm volatile("cp.async.cg.shared.global [%0], [%1], 16;\n" :: "r"(saddr), "l"(gaddr));
}
__device__ __forceinline__ void ldmatrix_x4(unsigned* r, unsigned addr) {
    asm volatile("ldmatrix.sync.aligned.m8n8.x4.shared.b16 {%0,%1,%2,%3}, [%4];\n"
                 : "=r"(r[0]), "=r"(r[1]), "=r"(r[2]), "=r"(r[3]) : "r"(addr));
}
__device__ __forceinline__ void mma_f16(float* d, const unsigned* a, const unsigned* b) {
    asm volatile("mma.sync.aligned.m16n8k16.row.col.f32.f16.f16.f32 "
                 "{%0,%1,%2,%3}, {%4,%5,%6,%7}, {%8,%9}, {%0,%1,%2,%3};\n"
                 : "+f"(d[0]), "+f"(d[1]), "+f"(d[2]), "+f"(d[3])
                 : "r"(a[0]), "r"(a[1]), "r"(a[2]), "r"(a[3]), "r"(b[0]), "r"(b[1]));
}
__device__ __forceinline__ unsigned pack_h16x2(__half lo, __half hi) {
    unsigned short ul = *(unsigned short*)&lo, uh = *(unsigned short*)&hi;
    return (unsigned)ul | ((unsigned)uh << 16);
}

// swizzled offset within a [rows x 32] half tile (64B rows, 4 x 16B chunks).
__device__ __forceinline__ unsigned swz32(int r, int ch) {
    return (unsigned)(r * 64 + ((ch ^ ((r >> 1) & 3)) << 4));
}

// ---------------- GEMM1, fused fp32->fp16 convert, single-pass fp16 MMA ------------
// h1 = relu(x@W1 + b1), output fp16 to g_hid16
// BM=128 BN=256(full HID) BK=32 (16 chunks), 512 threads (16 warps, 4m x 4n)
#define NCHUNK 16

__global__ __launch_bounds__(512) void gemm1_fused_kernel(
    const float* __restrict__ X, const float* __restrict__ b1)
{
    __shared__ __half sX[2][128 * 32];   // 8KB each
    __shared__ __half sW[2][256 * 32];   // 16KB each  (total 48KB)

    const int tid  = threadIdx.x;
    const int lane = tid & 31;
    const int wid  = tid >> 5;
    const int wm   = wid & 3;
    const int wn   = wid >> 2;
    const int m0 = blockIdx.x * 128;

    const int ar  = tid >> 2;
    const int ac8 = (tid & 3) * 8;
    int arow = m0 + ar; if (arow > NNODES - 1) arow = NNODES - 1;
    const float* xsrc = X + (size_t)arow * FIN + ac8;
    const unsigned stsOff = swz32(ar, tid & 3);

    const unsigned wOff0 = swz32(tid >> 2, tid & 3);
    const unsigned wOff1 = swz32((tid + 512) >> 2, tid & 3);
    const __half* wsrc0 = g_wT + (size_t)(tid >> 2) * FIN + (tid & 3) * 8;
    const __half* wsrc1 = g_wT + (size_t)((tid + 512) >> 2) * FIN + (tid & 3) * 8;

    float acc[2][8][4];
    #pragma unroll
    for (int mf = 0; mf < 2; mf++)
        #pragma unroll
        for (int nf = 0; nf < 8; nf++)
            #pragma unroll
            for (int q = 0; q < 4; q++) acc[mf][nf][q] = 0.0f;

    float4 xc0 = *(const float4*)xsrc;
    float4 xc1 = *(const float4*)(xsrc + 4);
    {
        cpasync16(smem_u32(sW[0]) + wOff0, wsrc0);
        cpasync16(smem_u32(sW[0]) + wOff1, wsrc1);
        asm volatile("cp.async.commit_group;\n" ::);
    }

    for (int i = 0; i < NCHUNK; i++) {
        const int buf = i & 1;
        float4 xn0, xn1;
        if (i + 1 < NCHUNK) {
            xn0 = *(const float4*)(xsrc + (i + 1) * 32);
            xn1 = *(const float4*)(xsrc + (i + 1) * 32 + 4);
            cpasync16(smem_u32(sW[buf ^ 1]) + wOff0, wsrc0 + (i + 1) * 32);
            cpasync16(smem_u32(sW[buf ^ 1]) + wOff1, wsrc1 + (i + 1) * 32);
            asm volatile("cp.async.commit_group;\n" ::);
            asm volatile("cp.async.wait_group 1;\n" ::);
        } else {
            asm volatile("cp.async.wait_group 0;\n" ::);
        }

        {
            uint4 v;
            v.x = pack_h16x2(__float2half_rn(xc0.x), __float2half_rn(xc0.y));
            v.y = pack_h16x2(__float2half_rn(xc0.z), __float2half_rn(xc0.w));
            v.z = pack_h16x2(__float2half_rn(xc1.x), __float2half_rn(xc1.y));
            v.w = pack_h16x2(__float2half_rn(xc1.z), __float2half_rn(xc1.w));
            *(uint4*)((char*)sX[buf] + stsOff) = v;
        }
        __syncthreads();

        {
            const unsigned xb = smem_u32(sX[buf]);
            const unsigned wb = smem_u32(sW[buf]);
            #pragma unroll
            for (int ks = 0; ks < 2; ks++) {
                unsigned fx[2][4];
                #pragma unroll
                for (int mf = 0; mf < 2; mf++) {
                    int row = wm * 32 + mf * 16 + (lane & 15);
                    int ch  = ks * 2 + (lane >> 4);
                    ldmatrix_x4(fx[mf], xb + swz32(row, ch));
                }
                unsigned fw[8][2];
                #pragma unroll
                for (int np = 0; np < 4; np++) {
                    int mat = lane >> 3, rr = lane & 7;
                    int n  = wn * 64 + np * 16 + (mat >> 1) * 8 + rr;
                    int ch = ks * 2 + (mat & 1);
                    unsigned t[4];
                    ldmatrix_x4(t, wb + swz32(n, ch));
                    fw[np * 2][0] = t[0];     fw[np * 2][1] = t[1];
                    fw[np * 2 + 1][0] = t[2]; fw[np * 2 + 1][1] = t[3];
                }
                #pragma unroll
                for (int mf = 0; mf < 2; mf++)
                    #pragma unroll
                    for (int nf = 0; nf < 8; nf++)
                        mma_f16(acc[mf][nf], fx[mf], fw[nf]);
            }
        }
        __syncthreads();
        xc0 = xn0; xc1 = xn1;
    }

    // epilogue: relu(acc + bias) -> g_hid16 fp16
    const int g  = lane >> 2;
    const int c2 = (lane & 3) * 2;
    #pragma unroll
    for (int mf = 0; mf < 2; mf++) {
        #pragma unroll
        for (int nf = 0; nf < 8; nf++) {
            int n = wn * 64 + nf * 8 + c2;
            float bn0 = b1[n], bn1 = b1[n + 1];
            int m_lo = m0 + wm * 32 + mf * 16 + g;
            int m_hi = m_lo + 8;
            if (m_lo < NNODES) {
                unsigned v = pack_h16x2(
                    __float2half_rn(fmaxf(acc[mf][nf][0] + bn0, 0.0f)),
                    __float2half_rn(fmaxf(acc[mf][nf][1] + bn1, 0.0f)));
                *(unsigned*)&g_hid16[(size_t)m_lo * HID + n] = v;
            }
            if (m_hi < NNODES) {
                unsigned v = pack_h16x2(
                    __float2half_rn(fmaxf(acc[mf][nf][2] + bn0, 0.0f)),
                    __float2half_rn(fmaxf(acc[mf][nf][3] + bn1, 0.0f)));
                *(unsigned*)&g_hid16[(size_t)m_hi * HID + n] = v;
            }
        }
    }
}

// ---------------- GEMM2: h = hid @ W2 + b2  (reads fp16 hid, writes fp16 h) -------
__global__ __launch_bounds__(256) void gemm2_kernel(
    const float* __restrict__ W2, const float* __restrict__ b2)
{
    __shared__ float Hs[32][65];
    __shared__ float Ws[32][40];

    int tid = threadIdx.x;
    int m0 = blockIdx.x * 64;
    int tx = tid & 7;        // 8 -> 5 cols each
    int ty = tid >> 3;       // 32 -> 2 rows each

    float acc[2][5];
    #pragma unroll
    for (int r = 0; r < 2; r++)
        #pragma unroll
        for (int j = 0; j < 5; j++) acc[r][j] = 0.0f;

    for (int k0 = 0; k0 < HID; k0 += 32) {
        {
            int kk = tid & 31;
            int mb = tid >> 5;
            #pragma unroll
            for (int mi = 0; mi < 8; mi++) {
                int m = mi * 8 + mb;
                float v = 0.0f;
                if (m0 + m < NNODES)
                    v = __half2float(g_hid16[(size_t)(m0 + m) * HID + k0 + kk]);
                Hs[kk][m] = v;
            }
        }
        #pragma unroll
        for (int l = 0; l < 5; l++) {
            int idx = tid + l * 256;
            int kr = idx / 40;
            int n = idx - kr * 40;
            Ws[kr][n] = W2[(size_t)(k0 + kr) * NC + n];
        }
        __syncthreads();

        #pragma unroll
        for (int k = 0; k < 32; k++) {
            float a0 = Hs[k][ty * 2];
            float a1 = Hs[k][ty * 2 + 1];
            #pragma unroll
            for (int j = 0; j < 5; j++) {
                float b = Ws[k][tx * 5 + j];
                acc[0][j] += a0 * b;
                acc[1][j] += a1 * b;
            }
        }
        __syncthreads();
    }

    #pragma unroll
    for (int r = 0; r < 2; r++) {
        int m = m0 + ty * 2 + r;
        if (m < NNODES) {
            #pragma unroll
            for (int j = 0; j < 5; j++) {
                int n = tx * 5 + j;
                g_h16[(size_t)m * NC + n] = __float2half_rn(acc[r][j] + b2[n]);
            }
        }
    }
}

// ---------------- fp16 gather helper ----------------
__device__ __forceinline__ float4 ldz16(const __half* p) {
    uint2 raw = *(const uint2*)p;
    __half2 a = *(__half2*)&raw.x;
    __half2 b = *(__half2*)&raw.y;
    float2 fa = __half22float2(a), fb = __half22float2(b);
    return make_float4(fa.x, fa.y, fb.x, fb.y);
}

// ---------------- APPNP step (fp16 z): zout = 0.9*A_norm*zin + 0.1*h --------------
__global__ __launch_bounds__(256) void spmm16_kernel(int srcSel, int dstSel) {
    const __half* zin  = (srcSel == 0) ? g_h16 : (srcSel == 1 ? g_z16A : g_z16B);
    __half*       zout = (dstSel == 1) ? g_z16A : g_z16B;

    int w = (blockIdx.x * blockDim.x + threadIdx.x) >> 5;
    int lane = threadIdx.x & 31;
    if (w >= NNODES) return;
    int s = g_rowptr[w];
    int e = g_rowptr[w + 1];

    int sub = lane / 10;
    int cg  = lane - sub * 10;

    float4 acc = make_float4(0.f, 0.f, 0.f, 0.f);
    if (sub < 3) {
        #pragma unroll 4
        for (int j = s + sub; j < e; j += 3) {
            int2 ed = __ldg(&g_edge[j]);
            float wt = __int_as_float(ed.y);
            float4 zv = ldz16(zin + (size_t)ed.x * NC + cg * 4);
            acc.x += wt * zv.x;
            acc.y += wt * zv.y;
            acc.z += wt * zv.z;
            acc.w += wt * zv.w;
        }
    }

    float tx1 = __shfl_down_sync(0xffffffff, acc.x, 10);
    float ty1 = __shfl_down_sync(0xffffffff, acc.y, 10);
    float tz1 = __shfl_down_sync(0xffffffff, acc.z, 10);
    float tw1 = __shfl_down_sync(0xffffffff, acc.w, 10);
    float tx2 = __shfl_down_sync(0xffffffff, acc.x, 20);
    float ty2 = __shfl_down_sync(0xffffffff, acc.y, 20);
    float tz2 = __shfl_down_sync(0xffffffff, acc.z, 20);
    float tw2 = __shfl_down_sync(0xffffffff, acc.w, 20);

    if (lane < 10) {
        acc.x += tx1 + tx2;
        acc.y += ty1 + ty2;
        acc.z += tz1 + tz2;
        acc.w += tw1 + tw2;

        float dv = g_dinv[w];
        float ws = dv * dv;
        float4 zr = ldz16(zin + (size_t)w * NC + cg * 4);
        acc.x += ws * zr.x;
        acc.y += ws * zr.y;
        acc.z += ws * zr.z;
        acc.w += ws * zr.w;

        float4 hr = ldz16(g_h16 + (size_t)w * NC + cg * 4);
        float ox = (1.0f - ALPHA) * acc.x + ALPHA * hr.x;
        float oy = (1.0f - ALPHA) * acc.y + ALPHA * hr.y;
        float oz = (1.0f - ALPHA) * acc.z + ALPHA * hr.z;
        float ow = (1.0f - ALPHA) * acc.w + ALPHA * hr.w;
        __half2 q0 = __floats2half2_rn(ox, oy);
        __half2 q1 = __floats2half2_rn(oz, ow);
        uint2 packed = make_uint2(*(unsigned*)&q0, *(unsigned*)&q1);
        *(uint2*)(zout + (size_t)w * NC + cg * 4) = packed;
    }
}

// ---------------- final APPNP step fused with log_softmax -> out fp32 --------------
__global__ __launch_bounds__(256) void spmm_last_kernel(float* __restrict__ out) {
    const __half* zin = g_z16A;    // step 9 output

    int w = (blockIdx.x * blockDim.x + threadIdx.x) >> 5;
    int lane = threadIdx.x & 31;
    if (w >= NNODES) return;
    int s = g_rowptr[w];
    int e = g_rowptr[w + 1];

    int sub = lane / 10;
    int cg  = lane - sub * 10;

    float4 acc = make_float4(0.f, 0.f, 0.f, 0.f);
    if (sub < 3) {
        #pragma unroll 4
        for (int j = s + sub; j < e; j += 3) {
            int2 ed = __ldg(&g_edge[j]);
            float wt = __int_as_float(ed.y);
            float4 zv = ldz16(zin + (size_t)ed.x * NC + cg * 4);
            acc.x += wt * zv.x;
            acc.y += wt * zv.y;
            acc.z += wt * zv.z;
            acc.w += wt * zv.w;
        }
    }

    float tx1 = __shfl_down_sync(0xffffffff, acc.x, 10);
    float ty1 = __shfl_down_sync(0xffffffff, acc.y, 10);
    float tz1 = __shfl_down_sync(0xffffffff, acc.z, 10);
    float tw1 = __shfl_down_sync(0xffffffff, acc.w, 10);
    float tx2 = __shfl_down_sync(0xffffffff, acc.x, 20);
    float ty2 = __shfl_down_sync(0xffffffff, acc.y, 20);
    float tz2 = __shfl_down_sync(0xffffffff, acc.z, 20);
    float tw2 = __shfl_down_sync(0xffffffff, acc.w, 20);

    float ox = 0.f, oy = 0.f, oz = 0.f, ow = 0.f;
    float mloc = -3.4e38f;
    if (lane < 10) {
        acc.x += tx1 + tx2;
        acc.y += ty1 + ty2;
        acc.z += tz1 + tz2;
        acc.w += tw1 + tw2;

        float dv = g_dinv[w];
        float ws = dv * dv;
        float4 zr = ldz16(zin + (size_t)w * NC + cg * 4);
        acc.x += ws * zr.x;
        acc.y += ws * zr.y;
        acc.z += ws * zr.z;
        acc.w += ws * zr.w;

        float4 hr = ldz16(g_h16 + (size_t)w * NC + cg * 4);
        ox = (1.0f - ALPHA) * acc.x + ALPHA * hr.x;
        oy = (1.0f - ALPHA) * acc.y + ALPHA * hr.y;
        oz = (1.0f - ALPHA) * acc.z + ALPHA * hr.z;
        ow = (1.0f - ALPHA) * acc.w + ALPHA * hr.w;
        mloc = fmaxf(fmaxf(ox, oy), fmaxf(oz, ow));
    }

    #pragma unroll
    for (int off = 8; off > 0; off >>= 1)
        mloc = fmaxf(mloc, __shfl_xor_sync(0xffffffff, mloc, off, 16));

    float sloc = 0.0f;
    if (lane < 10)
        sloc = __expf(ox - mloc) + __expf(oy - mloc) + __expf(oz - mloc) + __expf(ow - mloc);
    #pragma unroll
    for (int off = 8; off > 0; off >>= 1)
        sloc += __shfl_xor_sync(0xffffffff, sloc, off, 16);

    if (lane < 10) {
        float lse = mloc + logf(sloc);
        float4 o = make_float4(ox - lse, oy - lse, oz - lse, ow - lse);
        *(float4*)(out + (size_t)w * NC + cg * 4) = o;
    }
}

// ---------------- launch ----------------
extern "C" void kernel_launch(void* const* d_in, const int* in_sizes, int n_in,
                              void* d_out, int out_size) {
    const float* x  = (const float*)d_in[0];
    const float* W1 = (const float*)d_in[1];
    const float* b1 = (const float*)d_in[2];
    const float* W2 = (const float*)d_in[3];
    const float* b2 = (const float*)d_in[4];
    const int*   ei = (const int*)d_in[5];
    float* out = (float*)d_out;
    int E = in_sizes[5] / 2;

    // side stream for graph preprocessing (independent of MLP until spmm)
    static cudaStream_t s2 = nullptr;
    static cudaEvent_t evFork = nullptr, evJoin = nullptr;
    if (s2 == nullptr) {
        cudaStreamCreateWithFlags(&s2, cudaStreamNonBlocking);
        cudaEventCreateWithFlags(&evFork, cudaEventDisableTiming);
        cudaEventCreateWithFlags(&evJoin, cudaEventDisableTiming);
    }

    cudaEventRecord(evFork, 0);
    cudaStreamWaitEvent(s2, evFork, 0);

    // --- side stream: graph preprocessing -> CSR + normalized weights ---
    zero_deg_kernel<<<(NNODES + 255) / 256, 256, 0, s2>>>();
    count_deg_kernel<<<(E + 255) / 256, 256, 0, s2>>>(ei, E);
    scan_kernel<<<1, 1024, 0, s2>>>(E);
    scatter_kernel<<<(E + 255) / 256, 256, 0, s2>>>(ei, E);
    cudaEventRecord(evJoin, s2);

    // --- main stream: MLP encoder (overlaps with preprocessing) ---
    convert_w_kernel<<<(FIN * HID + 255) / 256, 256>>>(W1);
    gemm1_fused_kernel<<<(NNODES + 127) / 128, 512>>>(x, b1);
    gemm2_kernel<<<(NNODES + 63) / 64, 256>>>(W2, b2);

    // join: spmm needs both g_h16 (main) and CSR (s2)
    cudaStreamWaitEvent(0, evJoin, 0);

    // steps 1..9 on fp16 z; step 10 fused with log_softmax
    int spmmGrid = (NNODES * 32 + 255) / 256;
    for (int i = 1; i <= KSTEPS - 1; i++) {
        int src = (i == 1) ? 0 : ((i & 1) ? 2 : 1);
        int dst = (i & 1) ? 1 : 2;
        spmm16_kernel<<<spmmGrid, 256>>>(src, dst);
    }
    spmm_last_kernel<<<spmmGrid, 256>>>(out);   // reads g_z16A (step-9 output)
}

// round 15
// speedup vs baseline: 1.0307x; 1.0307x over previous
#include <cuda_runtime.h>
#include <cuda_bf16.h>
#include <cuda_fp16.h>
#include <math.h>

#define NNODES 100000
#define FIN    512
#define HID    256
#define NC     40
#define KSTEPS 10
#define EMAX   3200000
#define ALPHA  0.1f

// ---------------- device scratch (no allocations allowed) ----------------
__device__ float g_hid[NNODES * HID];      // ~102 MB
__device__ float g_h  [NNODES * NC];       // 16 MB (fp32 h for injection)
__device__ __half g_h16 [NNODES * NC];     // 8 MB (fp16 h for step-1 gather)
__device__ __half g_z16A[NNODES * NC];     // 8 MB ping
__device__ __half g_z16B[NNODES * NC];     // 8 MB pong
__device__ float g_dinv[NNODES];
__device__ int   g_deg [NNODES];
__device__ int   g_rowptr[NNODES + 1];
__device__ int   g_fill[NNODES];
__device__ int2  g_edge[EMAX];             // (col, ew bits) packed

// fp16 W (transposed) for tensor-core gemm1 (x is fp16-converted in-kernel)
__device__ __half g_wT[HID * FIN];         // [n][k], 0.26 MB

// ---------------- graph preprocessing ----------------
__global__ void zero_deg_kernel() {
    int i = blockIdx.x * blockDim.x + threadIdx.x;
    if (i < NNODES) g_deg[i] = 0;
}

__global__ void count_deg_kernel(const int* __restrict__ ei, int E) {
    int e = blockIdx.x * blockDim.x + threadIdx.x;
    if (e < E) atomicAdd(&g_deg[ei[e]], 1);
}

__global__ void scan_kernel(int E) {
    const int T = 1024;
    const int CH = (NNODES + T - 1) / T;
    int t = threadIdx.x;
    int beg = t * CH;
    int end = beg + CH; if (end > NNODES) end = NNODES;
    if (beg > NNODES) beg = NNODES;

    int sum = 0;
    for (int i = beg; i < end; i++) sum += g_deg[i];

    __shared__ int sh[1024];
    sh[t] = sum;
    __syncthreads();
    for (int off = 1; off < T; off <<= 1) {
        int v = (t >= off) ? sh[t - off] : 0;
        __syncthreads();
        sh[t] += v;
        __syncthreads();
    }
    int offset = sh[t] - sum;

    int running = offset;
    for (int i = beg; i < end; i++) {
        g_rowptr[i] = running;
        g_fill[i]   = running;
        g_dinv[i]   = rsqrtf((float)(g_deg[i] + 1));   // +1 self-loop
        running += g_deg[i];
    }
    if (t == T - 1) g_rowptr[NNODES] = sh[T - 1];
}

__global__ void scatter_kernel(const int* __restrict__ ei, int E) {
    int e = blockIdx.x * blockDim.x + threadIdx.x;
    if (e >= E) return;
    int r = ei[e];          // destination
    int c = ei[E + e];      // source
    int pos = atomicAdd(&g_fill[r], 1);
    g_edge[pos] = make_int2(c, __float_as_int(g_dinv[r] * g_dinv[c]));
}

// ---------------- W fp16 conversion (tiny: 0.26 MB) ----------------
__global__ void convert_w_kernel(const float* __restrict__ W1) {
    int i = blockIdx.x * blockDim.x + threadIdx.x;     // over FIN*HID
    if (i >= FIN * HID) return;
    int k = i / HID, n = i - k * HID;
    g_wT[n * FIN + k] = __float2half_rn(W1[i]);
}

// ---------------- helpers for mma path ----------------
__device__ __forceinline__ unsigned smem_u32(const void* p) {
    return (unsigned)__cvta_generic_to_shared(p);
}
__device__ __forceinline__ void cpasync16(unsigned saddr, const void* gaddr) {
    asm volatile("cp.async.cg.shared.global [%0], [%1], 16;\n" :: "r"(saddr), "l"(gaddr));
}
__device__ __forceinline__ void ldmatrix_x4(unsigned* r, unsigned addr) {
    asm volatile("ldmatrix.sync.aligned.m8n8.x4.shared.b16 {%0,%1,%2,%3}, [%4];\n"
                 : "=r"(r[0]), "=r"(r[1]), "=r"(r[2]), "=r"(r[3]) : "r"(addr));
}
__device__ __forceinline__ void mma_f16(float* d, const unsigned* a, const unsigned* b) {
    asm volatile("mma.sync.aligned.m16n8k16.row.col.f32.f16.f16.f32 "
                 "{%0,%1,%2,%3}, {%4,%5,%6,%7}, {%8,%9}, {%0,%1,%2,%3};\n"
                 : "+f"(d[0]), "+f"(d[1]), "+f"(d[2]), "+f"(d[3])
                 : "r"(a[0]), "r"(a[1]), "r"(a[2]), "r"(a[3]), "r"(b[0]), "r"(b[1]));
}
__device__ __forceinline__ unsigned pack_h16x2(__half lo, __half hi) {
    unsigned short ul = *(unsigned short*)&lo, uh = *(unsigned short*)&hi;
    return (unsigned)ul | ((unsigned)uh << 16);
}

// swizzled offset within a [rows x 32] half tile (64B rows, 4 x 16B chunks).
__device__ __forceinline__ unsigned swz32(int r, int ch) {
    return (unsigned)(r * 64 + ((ch ^ ((r >> 1) & 3)) << 4));
}

// ---------------- GEMM1, fused fp32->fp16 convert, single-pass fp16 MMA ------------
// h1 = relu(x@W1 + b1) with x,W fp16, fp32 accum
// BM=128 BN=256(full HID) BK=32 (16 chunks), 512 threads (16 warps, 4m x 4n)
#define NCHUNK 16

__global__ __launch_bounds__(512) void gemm1_fused_kernel(
    const float* __restrict__ X, const float* __restrict__ b1)
{
    __shared__ __half sX[2][128 * 32];   // 8KB each
    __shared__ __half sW[2][256 * 32];   // 16KB each  (total 48KB)

    const int tid  = threadIdx.x;
    const int lane = tid & 31;
    const int wid  = tid >> 5;
    const int wm   = wid & 3;
    const int wn   = wid >> 2;
    const int m0 = blockIdx.x * 128;

    const int ar  = tid >> 2;
    const int ac8 = (tid & 3) * 8;
    int arow = m0 + ar; if (arow > NNODES - 1) arow = NNODES - 1;
    const float* xsrc = X + (size_t)arow * FIN + ac8;
    const unsigned stsOff = swz32(ar, tid & 3);

    const unsigned wOff0 = swz32(tid >> 2, tid & 3);
    const unsigned wOff1 = swz32((tid + 512) >> 2, tid & 3);
    const __half* wsrc0 = g_wT + (size_t)(tid >> 2) * FIN + (tid & 3) * 8;
    const __half* wsrc1 = g_wT + (size_t)((tid + 512) >> 2) * FIN + (tid & 3) * 8;

    float acc[2][8][4];
    #pragma unroll
    for (int mf = 0; mf < 2; mf++)
        #pragma unroll
        for (int nf = 0; nf < 8; nf++)
            #pragma unroll
            for (int q = 0; q < 4; q++) acc[mf][nf][q] = 0.0f;

    float4 xc0 = *(const float4*)xsrc;
    float4 xc1 = *(const float4*)(xsrc + 4);
    {
        cpasync16(smem_u32(sW[0]) + wOff0, wsrc0);
        cpasync16(smem_u32(sW[0]) + wOff1, wsrc1);
        asm volatile("cp.async.commit_group;\n" ::);
    }

    for (int i = 0; i < NCHUNK; i++) {
        const int buf = i & 1;
        float4 xn0, xn1;
        if (i + 1 < NCHUNK) {
            xn0 = *(const float4*)(xsrc + (i + 1) * 32);
            xn1 = *(const float4*)(xsrc + (i + 1) * 32 + 4);
            cpasync16(smem_u32(sW[buf ^ 1]) + wOff0, wsrc0 + (i + 1) * 32);
            cpasync16(smem_u32(sW[buf ^ 1]) + wOff1, wsrc1 + (i + 1) * 32);
            asm volatile("cp.async.commit_group;\n" ::);
            asm volatile("cp.async.wait_group 1;\n" ::);
        } else {
            asm volatile("cp.async.wait_group 0;\n" ::);
        }

        {
            uint4 v;
            v.x = pack_h16x2(__float2half_rn(xc0.x), __float2half_rn(xc0.y));
            v.y = pack_h16x2(__float2half_rn(xc0.z), __float2half_rn(xc0.w));
            v.z = pack_h16x2(__float2half_rn(xc1.x), __float2half_rn(xc1.y));
            v.w = pack_h16x2(__float2half_rn(xc1.z), __float2half_rn(xc1.w));
            *(uint4*)((char*)sX[buf] + stsOff) = v;
        }
        __syncthreads();

        {
            const unsigned xb = smem_u32(sX[buf]);
            const unsigned wb = smem_u32(sW[buf]);
            #pragma unroll
            for (int ks = 0; ks < 2; ks++) {
                unsigned fx[2][4];
                #pragma unroll
                for (int mf = 0; mf < 2; mf++) {
                    int row = wm * 32 + mf * 16 + (lane & 15);
                    int ch  = ks * 2 + (lane >> 4);
                    ldmatrix_x4(fx[mf], xb + swz32(row, ch));
                }
                unsigned fw[8][2];
                #pragma unroll
                for (int np = 0; np < 4; np++) {
                    int mat = lane >> 3, rr = lane & 7;
                    int n  = wn * 64 + np * 16 + (mat >> 1) * 8 + rr;
                    int ch = ks * 2 + (mat & 1);
                    unsigned t[4];
                    ldmatrix_x4(t, wb + swz32(n, ch));
                    fw[np * 2][0] = t[0];     fw[np * 2][1] = t[1];
                    fw[np * 2 + 1][0] = t[2]; fw[np * 2 + 1][1] = t[3];
                }
                #pragma unroll
                for (int mf = 0; mf < 2; mf++)
                    #pragma unroll
                    for (int nf = 0; nf < 8; nf++)
                        mma_f16(acc[mf][nf], fx[mf], fw[nf]);
            }
        }
        __syncthreads();
        xc0 = xn0; xc1 = xn1;
    }

    // epilogue: relu(acc + bias) -> g_hid fp32
    const int g  = lane >> 2;
    const int c2 = (lane & 3) * 2;
    #pragma unroll
    for (int mf = 0; mf < 2; mf++) {
        #pragma unroll
        for (int nf = 0; nf < 8; nf++) {
            int n = wn * 64 + nf * 8 + c2;
            float bn0 = b1[n], bn1 = b1[n + 1];
            int m_lo = m0 + wm * 32 + mf * 16 + g;
            int m_hi = m_lo + 8;
            if (m_lo < NNODES) {
                float2 v = make_float2(fmaxf(acc[mf][nf][0] + bn0, 0.0f),
                                       fmaxf(acc[mf][nf][1] + bn1, 0.0f));
                *(float2*)&g_hid[(size_t)m_lo * HID + n] = v;
            }
            if (m_hi < NNODES) {
                float2 v = make_float2(fmaxf(acc[mf][nf][2] + bn0, 0.0f),
                                       fmaxf(acc[mf][nf][3] + bn1, 0.0f));
                *(float2*)&g_hid[(size_t)m_hi * HID + n] = v;
            }
        }
    }
}

// ---------------- GEMM2: h = hid @ W2 + b2, writes fp32 + fp16 copies -------------
__global__ __launch_bounds__(256) void gemm2_kernel(
    const float* __restrict__ W2, const float* __restrict__ b2)
{
    __shared__ float Hs[32][65];
    __shared__ float Ws[32][40];

    int tid = threadIdx.x;
    int m0 = blockIdx.x * 64;
    int tx = tid & 7;        // 8 -> 5 cols each
    int ty = tid >> 3;       // 32 -> 2 rows each

    float acc[2][5];
    #pragma unroll
    for (int r = 0; r < 2; r++)
        #pragma unroll
        for (int j = 0; j < 5; j++) acc[r][j] = 0.0f;

    for (int k0 = 0; k0 < HID; k0 += 32) {
        {
            int kk = tid & 31;
            int mb = tid >> 5;
            #pragma unroll
            for (int mi = 0; mi < 8; mi++) {
                int m = mi * 8 + mb;
                float v = 0.0f;
                if (m0 + m < NNODES)
                    v = g_hid[(size_t)(m0 + m) * HID + k0 + kk];
                Hs[kk][m] = v;
            }
        }
        #pragma unroll
        for (int l = 0; l < 5; l++) {
            int idx = tid + l * 256;
            int kr = idx / 40;
            int n = idx - kr * 40;
            Ws[kr][n] = W2[(size_t)(k0 + kr) * NC + n];
        }
        __syncthreads();

        #pragma unroll
        for (int k = 0; k < 32; k++) {
            float a0 = Hs[k][ty * 2];
            float a1 = Hs[k][ty * 2 + 1];
            #pragma unroll
            for (int j = 0; j < 5; j++) {
                float b = Ws[k][tx * 5 + j];
                acc[0][j] += a0 * b;
                acc[1][j] += a1 * b;
            }
        }
        __syncthreads();
    }

    #pragma unroll
    for (int r = 0; r < 2; r++) {
        int m = m0 + ty * 2 + r;
        if (m < NNODES) {
            #pragma unroll
            for (int j = 0; j < 5; j++) {
                int n = tx * 5 + j;
                float v = acc[r][j] + b2[n];
                g_h[(size_t)m * NC + n] = v;
                g_h16[(size_t)m * NC + n] = __float2half_rn(v);
            }
        }
    }
}

// ---------------- fp16 gather helper ----------------
__device__ __forceinline__ float4 ldz16(const __half* p) {
    uint2 raw = *(const uint2*)p;
    __half2 a = *(__half2*)&raw.x;
    __half2 b = *(__half2*)&raw.y;
    float2 fa = __half22float2(a), fb = __half22float2(b);
    return make_float4(fa.x, fa.y, fb.x, fb.y);
}

#define SPMM_BLOCKS 1216   // 152 SM x 8 CTAs: persistent-strided, no wave tail

// ---------------- APPNP step (fp16 z): zout = 0.9*A_norm*zin + 0.1*h --------------
// persistent grid; each warp strides over rows; 3 edge sub-groups of 10 lanes
__global__ __launch_bounds__(256) void spmm16_kernel(int srcSel, int dstSel) {
    const __half* zin  = (srcSel == 0) ? g_h16 : (srcSel == 1 ? g_z16A : g_z16B);
    __half*       zout = (dstSel == 1) ? g_z16A : g_z16B;

    const int lane = threadIdx.x & 31;
    const int gw = (blockIdx.x * blockDim.x + threadIdx.x) >> 5;
    const int NW = (SPMM_BLOCKS * 256) >> 5;

    const int sub = lane / 10;          // 0..2 active, 3 idle (lanes 30,31)
    const int cg  = lane - sub * 10;

    for (int w = gw; w < NNODES; w += NW) {
        int s = g_rowptr[w];
        int e = g_rowptr[w + 1];

        float4 acc = make_float4(0.f, 0.f, 0.f, 0.f);
        if (sub < 3) {
            #pragma unroll 4
            for (int j = s + sub; j < e; j += 3) {
                int2 ed = __ldg(&g_edge[j]);
                float wt = __int_as_float(ed.y);
                float4 zv = ldz16(zin + (size_t)ed.x * NC + cg * 4);
                acc.x += wt * zv.x;
                acc.y += wt * zv.y;
                acc.z += wt * zv.z;
                acc.w += wt * zv.w;
            }
        }

        float tx1 = __shfl_down_sync(0xffffffff, acc.x, 10);
        float ty1 = __shfl_down_sync(0xffffffff, acc.y, 10);
        float tz1 = __shfl_down_sync(0xffffffff, acc.z, 10);
        float tw1 = __shfl_down_sync(0xffffffff, acc.w, 10);
        float tx2 = __shfl_down_sync(0xffffffff, acc.x, 20);
        float ty2 = __shfl_down_sync(0xffffffff, acc.y, 20);
        float tz2 = __shfl_down_sync(0xffffffff, acc.z, 20);
        float tw2 = __shfl_down_sync(0xffffffff, acc.w, 20);

        if (lane < 10) {
            acc.x += tx1 + tx2;
            acc.y += ty1 + ty2;
            acc.z += tz1 + tz2;
            acc.w += tw1 + tw2;

            float dv = g_dinv[w];
            float ws = dv * dv;
            float4 zr = ldz16(zin + (size_t)w * NC + cg * 4);
            acc.x += ws * zr.x;
            acc.y += ws * zr.y;
            acc.z += ws * zr.z;
            acc.w += ws * zr.w;

            float4 hr = *(const float4*)(g_h + (size_t)w * NC + cg * 4);
            float ox = (1.0f - ALPHA) * acc.x + ALPHA * hr.x;
            float oy = (1.0f - ALPHA) * acc.y + ALPHA * hr.y;
            float oz = (1.0f - ALPHA) * acc.z + ALPHA * hr.z;
            float ow = (1.0f - ALPHA) * acc.w + ALPHA * hr.w;
            __half2 q0 = __floats2half2_rn(ox, oy);
            __half2 q1 = __floats2half2_rn(oz, ow);
            uint2 packed = make_uint2(*(unsigned*)&q0, *(unsigned*)&q1);
            *(uint2*)(zout + (size_t)w * NC + cg * 4) = packed;
        }
    }
}

// ---------------- final APPNP step fused with log_softmax -> out fp32 --------------
__global__ __launch_bounds__(256) void spmm_last_kernel(float* __restrict__ out) {
    const __half* zin = g_z16A;    // step 9 output

    const int lane = threadIdx.x & 31;
    const int gw = (blockIdx.x * blockDim.x + threadIdx.x) >> 5;
    const int NW = (SPMM_BLOCKS * 256) >> 5;

    const int sub = lane / 10;
    const int cg  = lane - sub * 10;

    for (int w = gw; w < NNODES; w += NW) {
        int s = g_rowptr[w];
        int e = g_rowptr[w + 1];

        float4 acc = make_float4(0.f, 0.f, 0.f, 0.f);
        if (sub < 3) {
            #pragma unroll 4
            for (int j = s + sub; j < e; j += 3) {
                int2 ed = __ldg(&g_edge[j]);
                float wt = __int_as_float(ed.y);
                float4 zv = ldz16(zin + (size_t)ed.x * NC + cg * 4);
                acc.x += wt * zv.x;
                acc.y += wt * zv.y;
                acc.z += wt * zv.z;
                acc.w += wt * zv.w;
            }
        }

        float tx1 = __shfl_down_sync(0xffffffff, acc.x, 10);
        float ty1 = __shfl_down_sync(0xffffffff, acc.y, 10);
        float tz1 = __shfl_down_sync(0xffffffff, acc.z, 10);
        float tw1 = __shfl_down_sync(0xffffffff, acc.w, 10);
        float tx2 = __shfl_down_sync(0xffffffff, acc.x, 20);
        float ty2 = __shfl_down_sync(0xffffffff, acc.y, 20);
        float tz2 = __shfl_down_sync(0xffffffff, acc.z, 20);
        float tw2 = __shfl_down_sync(0xffffffff, acc.w, 20);

        float ox = 0.f, oy = 0.f, oz = 0.f, ow = 0.f;
        float mloc = -3.4e38f;
        if (lane < 10) {
            acc.x += tx1 + tx2;
            acc.y += ty1 + ty2;
            acc.z += tz1 + tz2;
            acc.w += tw1 + tw2;

            float dv = g_dinv[w];
            float ws = dv * dv;
            float4 zr = ldz16(zin + (size_t)w * NC + cg * 4);
            acc.x += ws * zr.x;
            acc.y += ws * zr.y;
            acc.z += ws * zr.z;
            acc.w += ws * zr.w;

            float4 hr = *(const float4*)(g_h + (size_t)w * NC + cg * 4);
            ox = (1.0f - ALPHA) * acc.x + ALPHA * hr.x;
            oy = (1.0f - ALPHA) * acc.y + ALPHA * hr.y;
            oz = (1.0f - ALPHA) * acc.z + ALPHA * hr.z;
            ow = (1.0f - ALPHA) * acc.w + ALPHA * hr.w;
            mloc = fmaxf(fmaxf(ox, oy), fmaxf(oz, ow));
        }

        #pragma unroll
        for (int off = 8; off > 0; off >>= 1)
            mloc = fmaxf(mloc, __shfl_xor_sync(0xffffffff, mloc, off, 16));

        float sloc = 0.0f;
        if (lane < 10)
            sloc = __expf(ox - mloc) + __expf(oy - mloc) + __expf(oz - mloc) + __expf(ow - mloc);
        #pragma unroll
        for (int off = 8; off > 0; off >>= 1)
            sloc += __shfl_xor_sync(0xffffffff, sloc, off, 16);

        if (lane < 10) {
            float lse = mloc + logf(sloc);
            float4 o = make_float4(ox - lse, oy - lse, oz - lse, ow - lse);
            *(float4*)(out + (size_t)w * NC + cg * 4) = o;
        }
    }
}

// ---------------- launch ----------------
extern "C" void kernel_launch(void* const* d_in, const int* in_sizes, int n_in,
                              void* d_out, int out_size) {
    const float* x  = (const float*)d_in[0];
    const float* W1 = (const float*)d_in[1];
    const float* b1 = (const float*)d_in[2];
    const float* W2 = (const float*)d_in[3];
    const float* b2 = (const float*)d_in[4];
    const int*   ei = (const int*)d_in[5];
    float* out = (float*)d_out;
    int E = in_sizes[5] / 2;

    // side stream for graph preprocessing (independent of MLP until spmm)
    static cudaStream_t s2 = nullptr;
    static cudaEvent_t evFork = nullptr, evJoin = nullptr;
    if (s2 == nullptr) {
        cudaStreamCreateWithFlags(&s2, cudaStreamNonBlocking);
        cudaEventCreateWithFlags(&evFork, cudaEventDisableTiming);
        cudaEventCreateWithFlags(&evJoin, cudaEventDisableTiming);
    }

    cudaEventRecord(evFork, 0);
    cudaStreamWaitEvent(s2, evFork, 0);

    // --- side stream: graph preprocessing -> CSR + normalized weights ---
    zero_deg_kernel<<<(NNODES + 255) / 256, 256, 0, s2>>>();
    count_deg_kernel<<<(E + 255) / 256, 256, 0, s2>>>(ei, E);
    scan_kernel<<<1, 1024, 0, s2>>>(E);
    scatter_kernel<<<(E + 255) / 256, 256, 0, s2>>>(ei, E);
    cudaEventRecord(evJoin, s2);

    // --- main stream: MLP encoder (overlaps with preprocessing) ---
    convert_w_kernel<<<(FIN * HID + 255) / 256, 256>>>(W1);
    gemm1_fused_kernel<<<(NNODES + 127) / 128, 512>>>(x, b1);
    gemm2_kernel<<<(NNODES + 63) / 64, 256>>>(W2, b2);

    // join: spmm needs both g_h/g_h16 (main) and CSR (s2)
    cudaStreamWaitEvent(0, evJoin, 0);

    // steps 1..9 on fp16 z (persistent-strided); step 10 fused with log_softmax
    for (int i = 1; i <= KSTEPS - 1; i++) {
        int src = (i == 1) ? 0 : ((i & 1) ? 2 : 1);
        int dst = (i & 1) ? 1 : 2;
        spmm16_kernel<<<SPMM_BLOCKS, 256>>>(src, dst);
    }
    spmm_last_kernel<<<SPMM_BLOCKS, 256>>>(out);   // reads g_z16A (step-9 output)
}

// round 16
// speedup vs baseline: 1.0420x; 1.0109x over previous
#include <cuda_runtime.h>
#include <cuda_bf16.h>
#include <cuda_fp16.h>
#include <math.h>

#define NNODES 100000
#define FIN    512
#define HID    256
#define NC     40
#define KSTEPS 10
#define EMAX   3200000
#define ALPHA  0.1f

// ---------------- device scratch (no allocations allowed) ----------------
__device__ float g_h  [NNODES * NC];       // 16 MB (fp32 h for injection)
__device__ __half g_h16 [NNODES * NC];     // 8 MB (fp16 h for step-1 gather)
__device__ __half g_z16A[NNODES * NC];     // 8 MB ping
__device__ __half g_z16B[NNODES * NC];     // 8 MB pong
__device__ float g_dinv[NNODES];
__device__ int   g_deg [NNODES];
__device__ int   g_rowptr[NNODES + 1];
__device__ int   g_fill[NNODES];
__device__ int2  g_edge[EMAX];             // (col, ew bits) packed

// fp16 W1 (transposed) for tensor-core gemm1
__device__ __half g_wT[HID * FIN];         // [n][k], 0.26 MB

// ---------------- graph preprocessing ----------------
__global__ void zero_deg_kernel() {
    int i = blockIdx.x * blockDim.x + threadIdx.x;
    if (i < NNODES) g_deg[i] = 0;
}

__global__ void count_deg_kernel(const int* __restrict__ ei, int E) {
    int e = blockIdx.x * blockDim.x + threadIdx.x;
    if (e < E) atomicAdd(&g_deg[ei[e]], 1);
}

__global__ void scan_kernel(int E) {
    const int T = 1024;
    const int CH = (NNODES + T - 1) / T;
    int t = threadIdx.x;
    int beg = t * CH;
    int end = beg + CH; if (end > NNODES) end = NNODES;
    if (beg > NNODES) beg = NNODES;

    int sum = 0;
    for (int i = beg; i < end; i++) sum += g_deg[i];

    __shared__ int sh[1024];
    sh[t] = sum;
    __syncthreads();
    for (int off = 1; off < T; off <<= 1) {
        int v = (t >= off) ? sh[t - off] : 0;
        __syncthreads();
        sh[t] += v;
        __syncthreads();
    }
    int offset = sh[t] - sum;

    int running = offset;
    for (int i = beg; i < end; i++) {
        g_rowptr[i] = running;
        g_fill[i]   = running;
        g_dinv[i]   = rsqrtf((float)(g_deg[i] + 1));   // +1 self-loop
        running += g_deg[i];
    }
    if (t == T - 1) g_rowptr[NNODES] = sh[T - 1];
}

__global__ void scatter_kernel(const int* __restrict__ ei, int E) {
    int e = blockIdx.x * blockDim.x + threadIdx.x;
    if (e >= E) return;
    int r = ei[e];          // destination
    int c = ei[E + e];      // source
    int pos = atomicAdd(&g_fill[r], 1);
    g_edge[pos] = make_int2(c, __float_as_int(g_dinv[r] * g_dinv[c]));
}

// ---------------- W1 fp16 conversion (tiny: 0.26 MB) ----------------
__global__ void convert_w_kernel(const float* __restrict__ W1) {
    int i = blockIdx.x * blockDim.x + threadIdx.x;     // over FIN*HID
    if (i >= FIN * HID) return;
    int k = i / HID, n = i - k * HID;
    g_wT[n * FIN + k] = __float2half_rn(W1[i]);
}

// ---------------- helpers for mma path ----------------
__device__ __forceinline__ unsigned smem_u32(const void* p) {
    return (unsigned)__cvta_generic_to_shared(p);
}
__device__ __forceinline__ void cpasync16(unsigned saddr, const void* gaddr) {
    asm volatile("cp.async.cg.shared.global [%0], [%1], 16;\n" :: "r"(saddr), "l"(gaddr));
}
__device__ __forceinline__ void ldmatrix_x4(unsigned* r, unsigned addr) {
    asm volatile("ldmatrix.sync.aligned.m8n8.x4.shared.b16 {%0,%1,%2,%3}, [%4];\n"
                 : "=r"(r[0]), "=r"(r[1]), "=r"(r[2]), "=r"(r[3]) : "r"(addr));
}
__device__ __forceinline__ void mma_f16(float* d, const unsigned* a, const unsigned* b) {
    asm volatile("mma.sync.aligned.m16n8k16.row.col.f32.f16.f16.f32 "
                 "{%0,%1,%2,%3}, {%4,%5,%6,%7}, {%8,%9}, {%0,%1,%2,%3};\n"
                 : "+f"(d[0]), "+f"(d[1]), "+f"(d[2]), "+f"(d[3])
                 : "r"(a[0]), "r"(a[1]), "r"(a[2]), "r"(a[3]), "r"(b[0]), "r"(b[1]));
}
__device__ __forceinline__ unsigned pack_h16x2(__half lo, __half hi) {
    unsigned short ul = *(unsigned short*)&lo, uh = *(unsigned short*)&hi;
    return (unsigned)ul | ((unsigned)uh << 16);
}

// swizzled offset within a [rows x 32] half tile (64B rows, 4 x 16B chunks).
__device__ __forceinline__ unsigned swz32(int r, int ch) {
    return (unsigned)(r * 64 + ((ch ^ ((r >> 1) & 3)) << 4));
}
// swizzled offset within a [rows x 256] half tile (512B rows, 16 x 16B chunks).
// ch ^= r&7 -> 8-row ldmatrix phases hit 8 consecutive distinct 16B slots.
__device__ __forceinline__ unsigned swz256(int r, int ch) {
    return (unsigned)(r * 512 + ((ch ^ (r & 7)) << 4));
}

// ---------------- GEMM1+GEMM2 fused: h = hid@W2+b2, hid = relu(x@W1+b1) ----------
// Phase A: BM=128 BN=256 BK=32 (16 chunks) fp16 MMA -> acc (hid tile in regs)
// Phase B: hid tile -> smem fp16, short MMA vs W2 -> h, write g_h/g_h16
// 512 threads (16 warps, 4m x 4n). Dynamic smem 88KB.
#define NCHUNK 16
#define G1_SMEM 90112   // 64KB sHid + 24KB sW2 (phase A uses first 48KB)

extern __shared__ __align__(1024) char dynsmem[];

__global__ __launch_bounds__(512) void gemm1_fused_kernel(
    const float* __restrict__ X, const float* __restrict__ b1,
    const float* __restrict__ W2, const float* __restrict__ b2)
{
    __half* sX[2] = { (__half*)dynsmem,           (__half*)(dynsmem + 8192)  };
    __half* sW[2] = { (__half*)(dynsmem + 16384), (__half*)(dynsmem + 32768) };

    const int tid  = threadIdx.x;
    const int lane = tid & 31;
    const int wid  = tid >> 5;
    const int wm   = wid & 3;
    const int wn   = wid >> 2;
    const int m0 = blockIdx.x * 128;

    const int ar  = tid >> 2;
    const int ac8 = (tid & 3) * 8;
    int arow = m0 + ar; if (arow > NNODES - 1) arow = NNODES - 1;
    const float* xsrc = X + (size_t)arow * FIN + ac8;
    const unsigned stsOff = swz32(ar, tid & 3);

    const unsigned wOff0 = swz32(tid >> 2, tid & 3);
    const unsigned wOff1 = swz32((tid + 512) >> 2, tid & 3);
    const __half* wsrc0 = g_wT + (size_t)(tid >> 2) * FIN + (tid & 3) * 8;
    const __half* wsrc1 = g_wT + (size_t)((tid + 512) >> 2) * FIN + (tid & 3) * 8;

    float acc[2][8][4];
    #pragma unroll
    for (int mf = 0; mf < 2; mf++)
        #pragma unroll
        for (int nf = 0; nf < 8; nf++)
            #pragma unroll
            for (int q = 0; q < 4; q++) acc[mf][nf][q] = 0.0f;

    float4 xc0 = *(const float4*)xsrc;
    float4 xc1 = *(const float4*)(xsrc + 4);
    {
        cpasync16(smem_u32(sW[0]) + wOff0, wsrc0);
        cpasync16(smem_u32(sW[0]) + wOff1, wsrc1);
        asm volatile("cp.async.commit_group;\n" ::);
    }

    for (int i = 0; i < NCHUNK; i++) {
        const int buf = i & 1;
        float4 xn0, xn1;
        if (i + 1 < NCHUNK) {
            xn0 = *(const float4*)(xsrc + (i + 1) * 32);
            xn1 = *(const float4*)(xsrc + (i + 1) * 32 + 4);
            cpasync16(smem_u32(sW[buf ^ 1]) + wOff0, wsrc0 + (i + 1) * 32);
            cpasync16(smem_u32(sW[buf ^ 1]) + wOff1, wsrc1 + (i + 1) * 32);
            asm volatile("cp.async.commit_group;\n" ::);
            asm volatile("cp.async.wait_group 1;\n" ::);
        } else {
            asm volatile("cp.async.wait_group 0;\n" ::);
        }

        {
            uint4 v;
            v.x = pack_h16x2(__float2half_rn(xc0.x), __float2half_rn(xc0.y));
            v.y = pack_h16x2(__float2half_rn(xc0.z), __float2half_rn(xc0.w));
            v.z = pack_h16x2(__float2half_rn(xc1.x), __float2half_rn(xc1.y));
            v.w = pack_h16x2(__float2half_rn(xc1.z), __float2half_rn(xc1.w));
            *(uint4*)((char*)sX[buf] + stsOff) = v;
        }
        __syncthreads();

        {
            const unsigned xb = smem_u32(sX[buf]);
            const unsigned wb = smem_u32(sW[buf]);
            #pragma unroll
            for (int ks = 0; ks < 2; ks++) {
                unsigned fx[2][4];
                #pragma unroll
                for (int mf = 0; mf < 2; mf++) {
                    int row = wm * 32 + mf * 16 + (lane & 15);
                    int ch  = ks * 2 + (lane >> 4);
                    ldmatrix_x4(fx[mf], xb + swz32(row, ch));
                }
                unsigned fw[8][2];
                #pragma unroll
                for (int np = 0; np < 4; np++) {
                    int mat = lane >> 3, rr = lane & 7;
                    int n  = wn * 64 + np * 16 + (mat >> 1) * 8 + rr;
                    int ch = ks * 2 + (mat & 1);
                    unsigned t[4];
                    ldmatrix_x4(t, wb + swz32(n, ch));
                    fw[np * 2][0] = t[0];     fw[np * 2][1] = t[1];
                    fw[np * 2 + 1][0] = t[2]; fw[np * 2 + 1][1] = t[3];
                }
                #pragma unroll
                for (int mf = 0; mf < 2; mf++)
                    #pragma unroll
                    for (int nf = 0; nf < 8; nf++)
                        mma_f16(acc[mf][nf], fx[mf], fw[nf]);
            }
        }
        __syncthreads();
        xc0 = xn0; xc1 = xn1;
    }

    // ---------------- phase B: fused gemm2 ----------------
    __half* sHid = (__half*)dynsmem;             // [128][256] swizzled, 64KB
    __half* sW2  = (__half*)(dynsmem + 65536);   // [48][256]  swizzled, 24KB

    // load W2^T (fp32 [256][40] -> fp16 [40][256]); rows 40..47 left as garbage
    // (never fed to an MMA)
    for (int i2 = tid; i2 < 256 * 40; i2 += 512) {
        int k = i2 / 40, n = i2 - k * 40;
        unsigned off = swz256(n, k >> 3) + (k & 7) * 2;
        *(__half*)((char*)sW2 + off) = __float2half_rn(W2[i2]);
    }

    // relu(acc+b1) -> fp16 -> sHid (each warp writes its 32x64 subtile)
    {
        const int g  = lane >> 2;
        const int c2 = (lane & 3) * 2;
        #pragma unroll
        for (int mf = 0; mf < 2; mf++) {
            #pragma unroll
            for (int nf = 0; nf < 8; nf++) {
                int c = wn * 64 + nf * 8 + c2;
                float bn0 = b1[c], bn1 = b1[c + 1];
                int r_lo = wm * 32 + mf * 16 + g;
                int r_hi = r_lo + 8;
                unsigned v_lo = pack_h16x2(
                    __float2half_rn(fmaxf(acc[mf][nf][0] + bn0, 0.0f)),
                    __float2half_rn(fmaxf(acc[mf][nf][1] + bn1, 0.0f)));
                unsigned v_hi = pack_h16x2(
                    __float2half_rn(fmaxf(acc[mf][nf][2] + bn0, 0.0f)),
                    __float2half_rn(fmaxf(acc[mf][nf][3] + bn1, 0.0f)));
                *(unsigned*)((char*)sHid + swz256(r_lo, c >> 3) + (c & 7) * 2) = v_lo;
                *(unsigned*)((char*)sHid + swz256(r_hi, c >> 3) + (c & 7) * 2) = v_hi;
            }
        }
    }
    __syncthreads();

    // second GEMM: warps 0..7, warp j -> rows j*16..+16, cols 0..39, K=256
    if (wid < 8) {
        const unsigned hb = smem_u32(sHid);
        const unsigned wb2 = smem_u32(sW2);
        float hacc[5][4];
        #pragma unroll
        for (int nf = 0; nf < 5; nf++)
            #pragma unroll
            for (int q = 0; q < 4; q++) hacc[nf][q] = 0.0f;

        #pragma unroll 4
        for (int ks = 0; ks < 16; ks++) {
            unsigned fa[4];
            {
                int row = wid * 16 + (lane & 15);
                int ch  = ks * 2 + (lane >> 4);
                ldmatrix_x4(fa, hb + swz256(row, ch));
            }
            unsigned fb[6][2];
            #pragma unroll
            for (int np = 0; np < 3; np++) {
                int mat = lane >> 3, rr = lane & 7;
                int nrow = np * 16 + (mat >> 1) * 8 + rr;
                int ch = ks * 2 + (mat & 1);
                unsigned t[4];
                ldmatrix_x4(t, wb2 + swz256(nrow, ch));
                fb[np * 2][0] = t[0];     fb[np * 2][1] = t[1];
                fb[np * 2 + 1][0] = t[2]; fb[np * 2 + 1][1] = t[3];
            }
            #pragma unroll
            for (int nf = 0; nf < 5; nf++)
                mma_f16(hacc[nf], fa, fb[nf]);
        }

        // epilogue: h = hacc + b2 -> g_h (fp32) + g_h16 (fp16)
        const int g  = lane >> 2;
        const int c2 = (lane & 3) * 2;
        #pragma unroll
        for (int nf = 0; nf < 5; nf++) {
            int n = nf * 8 + c2;
            float bn0 = b2[n], bn1 = b2[n + 1];
            int m_lo = m0 + wid * 16 + g;
            int m_hi = m_lo + 8;
            if (m_lo < NNODES) {
                float v0 = hacc[nf][0] + bn0, v1 = hacc[nf][1] + bn1;
                *(float2*)&g_h[(size_t)m_lo * NC + n] = make_float2(v0, v1);
                *(unsigned*)&g_h16[(size_t)m_lo * NC + n] =
                    pack_h16x2(__float2half_rn(v0), __float2half_rn(v1));
            }
            if (m_hi < NNODES) {
                float v0 = hacc[nf][2] + bn0, v1 = hacc[nf][3] + bn1;
                *(float2*)&g_h[(size_t)m_hi * NC + n] = make_float2(v0, v1);
                *(unsigned*)&g_h16[(size_t)m_hi * NC + n] =
                    pack_h16x2(__float2half_rn(v0), __float2half_rn(v1));
            }
        }
    }
}

// ---------------- fp16 gather helper ----------------
__device__ __forceinline__ float4 ldz16(const __half* p) {
    uint2 raw = *(const uint2*)p;
    __half2 a = *(__half2*)&raw.x;
    __half2 b = *(__half2*)&raw.y;
    float2 fa = __half22float2(a), fb = __half22float2(b);
    return make_float4(fa.x, fa.y, fb.x, fb.y);
}

#define SPMM_BLOCKS 1216   // 152 SM x 8 CTAs: persistent-strided

// ---------------- APPNP step (fp16 z): zout = 0.9*A_norm*zin + 0.1*h --------------
__global__ __launch_bounds__(256) void spmm16_kernel(int srcSel, int dstSel) {
    const __half* zin  = (srcSel == 0) ? g_h16 : (srcSel == 1 ? g_z16A : g_z16B);
    __half*       zout = (dstSel == 1) ? g_z16A : g_z16B;

    const int lane = threadIdx.x & 31;
    const int gw = (blockIdx.x * blockDim.x + threadIdx.x) >> 5;
    const int NW = (SPMM_BLOCKS * 256) >> 5;

    const int sub = lane / 10;
    const int cg  = lane - sub * 10;

    for (int w = gw; w < NNODES; w += NW) {
        int s = g_rowptr[w];
        int e = g_rowptr[w + 1];

        float4 acc = make_float4(0.f, 0.f, 0.f, 0.f);
        if (sub < 3) {
            #pragma unroll 4
            for (int j = s + sub; j < e; j += 3) {
                int2 ed = __ldg(&g_edge[j]);
                float wt = __int_as_float(ed.y);
                float4 zv = ldz16(zin + (size_t)ed.x * NC + cg * 4);
                acc.x += wt * zv.x;
                acc.y += wt * zv.y;
                acc.z += wt * zv.z;
                acc.w += wt * zv.w;
            }
        }

        float tx1 = __shfl_down_sync(0xffffffff, acc.x, 10);
        float ty1 = __shfl_down_sync(0xffffffff, acc.y, 10);
        float tz1 = __shfl_down_sync(0xffffffff, acc.z, 10);
        float tw1 = __shfl_down_sync(0xffffffff, acc.w, 10);
        float tx2 = __shfl_down_sync(0xffffffff, acc.x, 20);
        float ty2 = __shfl_down_sync(0xffffffff, acc.y, 20);
        float tz2 = __shfl_down_sync(0xffffffff, acc.z, 20);
        float tw2 = __shfl_down_sync(0xffffffff, acc.w, 20);

        if (lane < 10) {
            acc.x += tx1 + tx2;
            acc.y += ty1 + ty2;
            acc.z += tz1 + tz2;
            acc.w += tw1 + tw2;

            float dv = g_dinv[w];
            float ws = dv * dv;
            float4 zr = ldz16(zin + (size_t)w * NC + cg * 4);
            acc.x += ws * zr.x;
            acc.y += ws * zr.y;
            acc.z += ws * zr.z;
            acc.w += ws * zr.w;

            float4 hr = *(const float4*)(g_h + (size_t)w * NC + cg * 4);
            float ox = (1.0f - ALPHA) * acc.x + ALPHA * hr.x;
            float oy = (1.0f - ALPHA) * acc.y + ALPHA * hr.y;
            float oz = (1.0f - ALPHA) * acc.z + ALPHA * hr.z;
            float ow = (1.0f - ALPHA) * acc.w + ALPHA * hr.w;
            __half2 q0 = __floats2half2_rn(ox, oy);
            __half2 q1 = __floats2half2_rn(oz, ow);
            uint2 packed = make_uint2(*(unsigned*)&q0, *(unsigned*)&q1);
            *(uint2*)(zout + (size_t)w * NC + cg * 4) = packed;
        }
    }
}

// ---------------- final APPNP step fused with log_softmax -> out fp32 --------------
__global__ __launch_bounds__(256) void spmm_last_kernel(float* __restrict__ out) {
    const __half* zin = g_z16A;    // step 9 output

    const int lane = threadIdx.x & 31;
    const int gw = (blockIdx.x * blockDim.x + threadIdx.x) >> 5;
    const int NW = (SPMM_BLOCKS * 256) >> 5;

    const int sub = lane / 10;
    const int cg  = lane - sub * 10;

    for (int w = gw; w < NNODES; w += NW) {
        int s = g_rowptr[w];
        int e = g_rowptr[w + 1];

        float4 acc = make_float4(0.f, 0.f, 0.f, 0.f);
        if (sub < 3) {
            #pragma unroll 4
            for (int j = s + sub; j < e; j += 3) {
                int2 ed = __ldg(&g_edge[j]);
                float wt = __int_as_float(ed.y);
                float4 zv = ldz16(zin + (size_t)ed.x * NC + cg * 4);
                acc.x += wt * zv.x;
                acc.y += wt * zv.y;
                acc.z += wt * zv.z;
                acc.w += wt * zv.w;
            }
        }

        float tx1 = __shfl_down_sync(0xffffffff, acc.x, 10);
        float ty1 = __shfl_down_sync(0xffffffff, acc.y, 10);
        float tz1 = __shfl_down_sync(0xffffffff, acc.z, 10);
        float tw1 = __shfl_down_sync(0xffffffff, acc.w, 10);
        float tx2 = __shfl_down_sync(0xffffffff, acc.x, 20);
        float ty2 = __shfl_down_sync(0xffffffff, acc.y, 20);
        float tz2 = __shfl_down_sync(0xffffffff, acc.z, 20);
        float tw2 = __shfl_down_sync(0xffffffff, acc.w, 20);

        float ox = 0.f, oy = 0.f, oz = 0.f, ow = 0.f;
        float mloc = -3.4e38f;
        if (lane < 10) {
            acc.x += tx1 + tx2;
            acc.y += ty1 + ty2;
            acc.z += tz1 + tz2;
            acc.w += tw1 + tw2;

            float dv = g_dinv[w];
            float ws = dv * dv;
            float4 zr = ldz16(zin + (size_t)w * NC + cg * 4);
            acc.x += ws * zr.x;
            acc.y += ws * zr.y;
            acc.z += ws * zr.z;
            acc.w += ws * zr.w;

            float4 hr = *(const float4*)(g_h + (size_t)w * NC + cg * 4);
            ox = (1.0f - ALPHA) * acc.x + ALPHA * hr.x;
            oy = (1.0f - ALPHA) * acc.y + ALPHA * hr.y;
            oz = (1.0f - ALPHA) * acc.z + ALPHA * hr.z;
            ow = (1.0f - ALPHA) * acc.w + ALPHA * hr.w;
            mloc = fmaxf(fmaxf(ox, oy), fmaxf(oz, ow));
        }

        #pragma unroll
        for (int off = 8; off > 0; off >>= 1)
            mloc = fmaxf(mloc, __shfl_xor_sync(0xffffffff, mloc, off, 16));

        float sloc = 0.0f;
        if (lane < 10)
            sloc = __expf(ox - mloc) + __expf(oy - mloc) + __expf(oz - mloc) + __expf(ow - mloc);
        #pragma unroll
        for (int off = 8; off > 0; off >>= 1)
            sloc += __shfl_xor_sync(0xffffffff, sloc, off, 16);

        if (lane < 10) {
            float lse = mloc + logf(sloc);
            float4 o = make_float4(ox - lse, oy - lse, oz - lse, ow - lse);
            *(float4*)(out + (size_t)w * NC + cg * 4) = o;
        }
    }
}

// ---------------- launch ----------------
extern "C" void kernel_launch(void* const* d_in, const int* in_sizes, int n_in,
                              void* d_out, int out_size) {
    const float* x  = (const float*)d_in[0];
    const float* W1 = (const float*)d_in[1];
    const float* b1 = (const float*)d_in[2];
    const float* W2 = (const float*)d_in[3];
    const float* b2 = (const float*)d_in[4];
    const int*   ei = (const int*)d_in[5];
    float* out = (float*)d_out;
    int E = in_sizes[5] / 2;

    // side stream + one-time setup (no device allocation)
    static cudaStream_t s2 = nullptr;
    static cudaEvent_t evFork = nullptr, evJoin = nullptr;
    if (s2 == nullptr) {
        cudaStreamCreateWithFlags(&s2, cudaStreamNonBlocking);
        cudaEventCreateWithFlags(&evFork, cudaEventDisableTiming);
        cudaEventCreateWithFlags(&evJoin, cudaEventDisableTiming);
        cudaFuncSetAttribute(gemm1_fused_kernel,
                             cudaFuncAttributeMaxDynamicSharedMemorySize, G1_SMEM);
    }

    cudaEventRecord(evFork, 0);
    cudaStreamWaitEvent(s2, evFork, 0);

    // --- side stream: graph preprocessing -> CSR + normalized weights ---
    zero_deg_kernel<<<(NNODES + 255) / 256, 256, 0, s2>>>();
    count_deg_kernel<<<(E + 255) / 256, 256, 0, s2>>>(ei, E);
    scan_kernel<<<1, 1024, 0, s2>>>(E);
    scatter_kernel<<<(E + 255) / 256, 256, 0, s2>>>(ei, E);
    cudaEventRecord(evJoin, s2);

    // --- main stream: fused MLP encoder (gemm1 + gemm2 in one kernel) ---
    convert_w_kernel<<<(FIN * HID + 255) / 256, 256>>>(W1);
    gemm1_fused_kernel<<<(NNODES + 127) / 128, 512, G1_SMEM>>>(x, b1, W2, b2);

    // join: spmm needs both g_h/g_h16 (main) and CSR (s2)
    cudaStreamWaitEvent(0, evJoin, 0);

    // steps 1..9 on fp16 z (persistent-strided); step 10 fused with log_softmax
    for (int i = 1; i <= KSTEPS - 1; i++) {
        int src = (i == 1) ? 0 : ((i & 1) ? 2 : 1);
        int dst = (i & 1) ? 1 : 2;
        spmm16_kernel<<<SPMM_BLOCKS, 256>>>(src, dst);
    }
    spmm_last_kernel<<<SPMM_BLOCKS, 256>>>(out);   // reads g_z16A (step-9 output)
}